// round 11
// baseline (speedup 1.0000x reference)
#include <cuda_runtime.h>
#include <cstdint>

#define Nn 100000
#define Ee 600000
#define EPSBN 1e-5f
#define SLOPE 0.2f

// ---------------- scratch ----------------
__device__ float g_HC[(size_t)Nn * 640];
__device__ float g_z[(size_t)Nn * 128];
__device__ float g_t[(size_t)Nn * 256];
__device__ float g_y[(size_t)Nn * 128];
__device__ float g_el[(size_t)Nn * 16];
__device__ float g_er[(size_t)Nn * 16];
__device__ float g_bnsum[8 * 256];
__device__ int   g_deg[Nn];
__device__ int   g_scan[Nn];
__device__ int   g_bsum[128];
__device__ int   g_rowptr[Nn + 1];
__device__ int   g_cursor[Nn];
__device__ int   g_srcs[Ee];
__device__ float g_W[425984];

__device__ __forceinline__ float to_tf32(float x) {
    float r;
    asm("cvt.rna.tf32.f32 %0, %1;" : "=f"(r) : "f"(x));
    return r;
}
__device__ __forceinline__ uint32_t smem_to_u32(const void* p) {
    uint32_t a;
    asm("{ .reg .u64 t; cvta.to.shared.u64 t, %1; cvt.u32.u64 %0, t; }" : "=r"(a) : "l"(p));
    return a;
}
__device__ __forceinline__ void cp16(uint32_t dst, const void* src, bool ok) {
    int sz = ok ? 16 : 0;
    asm volatile("cp.async.cg.shared.global [%0], [%1], 16, %2;"
                 :: "r"(dst), "l"(src), "r"(sz) : "memory");
}
#define CP_COMMIT() asm volatile("cp.async.commit_group;" ::: "memory")
#define CP_WAIT2() asm volatile("cp.async.wait_group 2;" ::: "memory")
#define CP_WAIT1() asm volatile("cp.async.wait_group 1;" ::: "memory")
#define CP_WAIT0() asm volatile("cp.async.wait_group 0;" ::: "memory")

#define MMA_TF32(d, av, bv)                                               \
    asm volatile(                                                         \
        "mma.sync.aligned.m16n8k8.row.col.f32.tf32.tf32.f32 "             \
        "{%0,%1,%2,%3},{%4,%5,%6,%7},{%8,%9},{%0,%1,%2,%3};"              \
        : "+f"((d)[0]), "+f"((d)[1]), "+f"((d)[2]), "+f"((d)[3])          \
        : "r"((av)[0]), "r"((av)[1]), "r"((av)[2]), "r"((av)[3]),         \
          "r"((bv)[0]), "r"((bv)[1]))

// ---------------- CSR build ----------------
__global__ void k_count(const int* __restrict__ dst) {
    int e = blockIdx.x * blockDim.x + threadIdx.x;
    if (e < Ee) atomicAdd(&g_deg[dst[e]], 1);
}
__global__ void k_scan1() {
    __shared__ int s[1024];
    int i = blockIdx.x * 1024 + threadIdx.x;
    int v = (i < Nn) ? g_deg[i] : 0;
    s[threadIdx.x] = v;
    __syncthreads();
    for (int off = 1; off < 1024; off <<= 1) {
        int t = (threadIdx.x >= off) ? s[threadIdx.x - off] : 0;
        __syncthreads();
        s[threadIdx.x] += t;
        __syncthreads();
    }
    if (i < Nn) g_scan[i] = s[threadIdx.x];
    if (threadIdx.x == 1023) g_bsum[blockIdx.x] = s[1023];
}
__global__ void k_scan2(int nb) {
    __shared__ int s[128];
    int v = (threadIdx.x < nb) ? g_bsum[threadIdx.x] : 0;
    s[threadIdx.x] = v;
    __syncthreads();
    for (int off = 1; off < 128; off <<= 1) {
        int t = (threadIdx.x >= off) ? s[threadIdx.x - off] : 0;
        __syncthreads();
        s[threadIdx.x] += t;
        __syncthreads();
    }
    g_bsum[threadIdx.x] = (threadIdx.x == 0) ? 0 : s[threadIdx.x - 1];
}
__global__ void k_finalize() {
    int i = blockIdx.x * blockDim.x + threadIdx.x;
    if (i >= Nn) return;
    int incl = g_scan[i] + g_bsum[i >> 10];
    g_rowptr[i + 1] = incl;
    g_cursor[i] = incl - g_deg[i];
    if (i == 0) g_rowptr[0] = 0;
}
__global__ void k_fill(const int* __restrict__ dst, const int* __restrict__ src) {
    int e = blockIdx.x * blockDim.x + threadIdx.x;
    if (e < Ee) {
        int d = dst[e];
        int p = atomicAdd(&g_cursor[d], 1);
        g_srcs[p] = src[e];
    }
}

// ---------------- all-weight cvt ----------------
__global__ void k_cvt_all(const float* __restrict__ gat_W, const float* __restrict__ ff_W1,
                          const float* __restrict__ ff_W2, const float* __restrict__ dec_W1,
                          const float* __restrict__ emb_W2) {
    int i = blockIdx.x * blockDim.x + threadIdx.x;
    if (i >= 425984) return;
    float v;
    if (i < 65536) v = gat_W[i];
    else if (i < 196608) v = ff_W1[i - 65536];
    else if (i < 327680) v = ff_W2[i - 196608];
    else if (i < 409600) v = dec_W1[i - 327680];
    else v = emb_W2[i - 409600];
    g_W[i] = to_tf32(v);
}

// ---------------- embed stage 1 ----------------
__global__ void k_embed1(const float* __restrict__ x,
                         const float* __restrict__ W1, const float* __restrict__ b1,
                         const float* __restrict__ b2,
                         const float* __restrict__ Ws, const float* __restrict__ bs) {
    int idx = blockIdx.x * blockDim.x + threadIdx.x;
    if (idx >= Nn * 128) return;
    int n = idx >> 7, c = idx & 127;
    float x0 = x[n * 2], x1 = x[n * 2 + 1];
    float tv = fmaf(x0, W1[c], fmaf(x1, W1[128 + c], b1[c]));
    g_t[idx] = tv > 0.f ? tv : 0.f;
    g_y[idx] = fmaf(x0, Ws[c], fmaf(x1, Ws[128 + c], bs[c] + b2[c]));
}

// ---------------- generic fused tf32 tensor GEMM (512 thr) ----------------
template <int RELU, int BIAS, int RES, int BN, int ELER, int AAFF, int RAFF, int DEC>
__global__ void __launch_bounds__(512, 2) k_tgemm(
    const float* __restrict__ A, int lda,
    const float* __restrict__ B,
    const float* __restrict__ bias,
    const float* __restrict__ Res, int ldres,
    float* __restrict__ C, int ldc,
    int Nrows, int Mred, int Kcols, float* bnslot,
    const float* affA, const float* affAg, const float* affAb,
    const float* affR, const float* affRg, const float* affRb,
    const float* al, const float* ar) {
    constexpr int S = 4;
    constexpr int ASTG = 128 * 20;
    constexpr int BSTG = 16 * 136;
    constexpr int STGF = S * ASTG + S * BSTG;
    constexpr int SCA = STGF, SHA = SCA + 640, SCR = SHA + 640, SHR = SCR + 128;
    constexpr int ALO = SHR + 128, ARO = ALO + 128;
    extern __shared__ float sm[];
    float* AsF = sm;
    float* BsF = sm + S * ASTG;

    const int tid = threadIdx.x;
    const int lane = tid & 31;
    const int wid = tid >> 5;
    const int bm = blockIdx.x * 128;
    const int bn = blockIdx.y * 128;

    const int m0 = (wid & 3) * 32;
    const int n0 = (wid >> 2) * 32;
    const int qrow = lane >> 2;
    const int qk = lane & 3;

    const int arow = tid >> 2;
    const int aseg = (tid & 3) * 4;
    const int brow = tid >> 5;
    const int bcol = (tid & 31) * 4;

    const int gr = bm + arow;
    const bool aok = gr < Nrows;
    const float* Asrc = A + (size_t)gr * lda + aseg;
    const float* Bsrc = B + (size_t)brow * Kcols + bn + bcol;
    const uint32_t adst = smem_to_u32(AsF) + (uint32_t)(arow * 20 + aseg) * 4u;
    const uint32_t bdst = smem_to_u32(BsF) + (uint32_t)(brow * 136 + bcol) * 4u;

    const int nIter = Mred >> 4;

#pragma unroll
    for (int s = 0; s < S - 1; s++) {
        if (s < nIter) {
            int kt = s << 4;
            cp16(adst + (uint32_t)(s * ASTG) * 4u, Asrc + kt, aok);
            cp16(bdst + (uint32_t)(s * BSTG) * 4u, Bsrc + (size_t)kt * Kcols, true);
        }
        CP_COMMIT();
    }

    const float invN = 1.f / (float)Nn;
    if (AAFF) {
        for (int k = tid; k < Mred; k += 512) {
            float scv = 1.f, shv = 0.f;
            const float *slot = nullptr, *gg = nullptr, *bb = nullptr;
            int c = k;
            if (AAFF == 1) { slot = affA; gg = affAg; bb = affAb; }
            else {
                int blk = k >> 7;
                c = k & 127;
                if (blk > 0) {
                    slot = g_bnsum + (size_t)(2 * (blk - 1) + 1) * 256;
                    gg = affAg + (blk - 1) * 128;
                    bb = affAb + (blk - 1) * 128;
                }
            }
            if (slot) {
                float mu = slot[c] * invN;
                float var = slot[c + 128] * invN - mu * mu;
                float rs = rsqrtf(var + EPSBN);
                scv = gg[c] * rs;
                shv = bb[c] - mu * scv;
            }
            sm[SCA + k] = scv;
            sm[SHA + k] = shv;
        }
    }
    if (RAFF) {
        if (tid < 128) {
            float mu = affR[tid] * invN;
            float var = affR[tid + 128] * invN - mu * mu;
            float rs = rsqrtf(var + EPSBN);
            float scv = affRg[tid] * rs;
            sm[SCR + tid] = scv;
            sm[SHR + tid] = affRb[tid] - mu * scv;
        }
    }
    if (ELER) {
        if (tid < 128) sm[ALO + tid] = al[tid];
        else if (tid < 256) sm[ARO + tid - 128] = ar[tid - 128];
    }
    if (DEC) {
        if (tid < 128) sm[ALO + tid] = al[tid];
    }

    float acc[2][4][4];
#pragma unroll
    for (int mi = 0; mi < 2; mi++)
#pragma unroll
        for (int ni = 0; ni < 4; ni++)
#pragma unroll
            for (int j = 0; j < 4; j++) acc[mi][ni][j] = 0.f;

    for (int it = 0; it < nIter; it++) {
        CP_WAIT2();
        __syncthreads();

        const int stg = it & (S - 1);
        const float* as = AsF + stg * ASTG;
        const float* bs = BsF + stg * BSTG;
#pragma unroll
        for (int ks = 0; ks < 2; ks++) {
            const int kbase = ks * 8;
            float sc0 = 1.f, sc1 = 1.f, sh0 = 0.f, sh1 = 0.f;
            if (AAFF) {
                int kg = (it << 4) + kbase + qk;
                sc0 = sm[SCA + kg]; sh0 = sm[SHA + kg];
                sc1 = sm[SCA + kg + 4]; sh1 = sm[SHA + kg + 4];
            }
            uint32_t a[2][4];
#pragma unroll
            for (int mi = 0; mi < 2; mi++) {
                const float* ap = as + (m0 + mi * 16 + qrow) * 20 + kbase + qk;
                if (AAFF) {
                    a[mi][0] = __float_as_uint(to_tf32(fmaf(ap[0], sc0, sh0)));
                    a[mi][1] = __float_as_uint(to_tf32(fmaf(ap[8 * 20], sc0, sh0)));
                    a[mi][2] = __float_as_uint(to_tf32(fmaf(ap[4], sc1, sh1)));
                    a[mi][3] = __float_as_uint(to_tf32(fmaf(ap[8 * 20 + 4], sc1, sh1)));
                } else {
                    a[mi][0] = __float_as_uint(to_tf32(ap[0]));
                    a[mi][1] = __float_as_uint(to_tf32(ap[8 * 20]));
                    a[mi][2] = __float_as_uint(to_tf32(ap[4]));
                    a[mi][3] = __float_as_uint(to_tf32(ap[8 * 20 + 4]));
                }
            }
            uint32_t b[4][2];
#pragma unroll
            for (int ni = 0; ni < 4; ni++) {
                const float* bp = bs + (kbase + qk) * 136 + n0 + ni * 8 + qrow;
                b[ni][0] = __float_as_uint(bp[0]);
                b[ni][1] = __float_as_uint(bp[4 * 136]);
            }
#pragma unroll
            for (int mi = 0; mi < 2; mi++)
#pragma unroll
                for (int ni = 0; ni < 4; ni++) MMA_TF32(acc[mi][ni], a[mi], b[ni]);
        }

        const int nx = it + S - 1;
        if (nx < nIter) {
            const int s = nx & (S - 1);
            const int kt = nx << 4;
            cp16(adst + (uint32_t)(s * ASTG) * 4u, Asrc + kt, aok);
            cp16(bdst + (uint32_t)(s * BSTG) * 4u, Bsrc + (size_t)kt * Kcols, true);
        }
        CP_COMMIT();
    }

    // epilogue
    float s0[4], s1[4], q0[4], q1[4];
    if (BN) {
#pragma unroll
        for (int ni = 0; ni < 4; ni++) { s0[ni] = 0.f; s1[ni] = 0.f; q0[ni] = 0.f; q1[ni] = 0.f; }
    }
#pragma unroll
    for (int mi = 0; mi < 2; mi++) {
#pragma unroll
        for (int half = 0; half < 2; half++) {
            int r = bm + m0 + mi * 16 + qrow + half * 8;
            bool rok = r < Nrows;
            float pd = 0.f;
#pragma unroll
            for (int ni = 0; ni < 4; ni++) {
                int gcl = n0 + ni * 8 + qk * 2;
                int gc = bn + gcl;
                float v0 = acc[mi][ni][half * 2 + 0];
                float v1 = acc[mi][ni][half * 2 + 1];
                if (BIAS) {
                    v0 += bias[gc];
                    v1 += bias[gc + 1];
                }
                if (RELU) {
                    v0 = fmaxf(v0, 0.f);
                    v1 = fmaxf(v1, 0.f);
                }
                if (RES && rok) {
                    const float* rp = Res + (size_t)r * ldres + gc;
                    float rv0 = rp[0], rv1 = rp[1];
                    if (RAFF) {
                        rv0 = fmaf(rv0, sm[SCR + gc], sm[SHR + gc]);
                        rv1 = fmaf(rv1, sm[SCR + gc + 1], sm[SHR + gc + 1]);
                    }
                    v0 += rv0;
                    v1 += rv1;
                }
                if (!DEC && rok) *(float2*)(C + (size_t)r * ldc + gc) = make_float2(v0, v1);
                if (BN && rok) {
                    s0[ni] += v0; q0[ni] += v0 * v0;
                    s1[ni] += v1; q1[ni] += v1 * v1;
                }
                if (DEC) pd = fmaf(v0, sm[ALO + gcl], fmaf(v1, sm[ALO + gcl + 1], pd));
                if (ELER) {
                    int h = (n0 >> 3) + ni;
                    float p = fmaf(v0, sm[ALO + h * 8 + qk * 2], v1 * sm[ALO + h * 8 + qk * 2 + 1]);
                    float q = fmaf(v0, sm[ARO + h * 8 + qk * 2], v1 * sm[ARO + h * 8 + qk * 2 + 1]);
                    p += __shfl_xor_sync(0xffffffffu, p, 1);
                    p += __shfl_xor_sync(0xffffffffu, p, 2);
                    q += __shfl_xor_sync(0xffffffffu, q, 1);
                    q += __shfl_xor_sync(0xffffffffu, q, 2);
                    if ((lane & 3) == 0 && rok) {
                        g_el[r * 16 + h] = p;
                        g_er[r * 16 + h] = q;
                    }
                }
            }
            if (DEC) {
                pd += __shfl_xor_sync(0xffffffffu, pd, 1);
                pd += __shfl_xor_sync(0xffffffffu, pd, 2);
                if ((lane & 3) == 0 && rok)
                    atomicAdd(C + r, pd + 0.25f * ar[0]);
            }
        }
    }

    if (BN) {
#pragma unroll
        for (int ni = 0; ni < 4; ni++) {
            s0[ni] += __shfl_xor_sync(0xffffffffu, s0[ni], 4);
            s0[ni] += __shfl_xor_sync(0xffffffffu, s0[ni], 8);
            s0[ni] += __shfl_xor_sync(0xffffffffu, s0[ni], 16);
            s1[ni] += __shfl_xor_sync(0xffffffffu, s1[ni], 4);
            s1[ni] += __shfl_xor_sync(0xffffffffu, s1[ni], 8);
            s1[ni] += __shfl_xor_sync(0xffffffffu, s1[ni], 16);
            q0[ni] += __shfl_xor_sync(0xffffffffu, q0[ni], 4);
            q0[ni] += __shfl_xor_sync(0xffffffffu, q0[ni], 8);
            q0[ni] += __shfl_xor_sync(0xffffffffu, q0[ni], 16);
            q1[ni] += __shfl_xor_sync(0xffffffffu, q1[ni], 4);
            q1[ni] += __shfl_xor_sync(0xffffffffu, q1[ni], 8);
            q1[ni] += __shfl_xor_sync(0xffffffffu, q1[ni], 16);
        }
        __syncthreads();
        if (lane < 4) {
            int mg = wid & 3;
#pragma unroll
            for (int ni = 0; ni < 4; ni++) {
                int c = n0 + ni * 8 + lane * 2;
                sm[mg * 128 + c] = s0[ni];
                sm[mg * 128 + c + 1] = s1[ni];
                sm[512 + mg * 128 + c] = q0[ni];
                sm[512 + mg * 128 + c + 1] = q1[ni];
            }
        }
        __syncthreads();
        if (tid < 256) {
            int c = tid & 127, st = tid >> 7;
            float v = sm[st * 512 + c] + sm[st * 512 + 128 + c] +
                      sm[st * 512 + 256 + c] + sm[st * 512 + 384 + c];
            atomicAdd(bnslot + st * 128 + c, v);
        }
    }
}

// ---------------- fused FF kernel (triple-buffered weights, 1 barrier/iter) ----------------
// smem floats: Y[128][132]=16896 | T[128][260]=33280 | W 3*2176=6528 | SCA 128 | SHA 128 | SB1 256
__global__ void __launch_bounds__(512, 1) k_ff(
    const float* __restrict__ y,
    const float* __restrict__ W1, const float* __restrict__ b1v,
    const float* __restrict__ W2, const float* __restrict__ b2v,
    float* __restrict__ C, int ldc,
    const float* __restrict__ slot1, const float* __restrict__ g1, const float* __restrict__ bb1,
    float* __restrict__ bnslot) {
    constexpr int YOFF = 0;
    constexpr int TOFF = 16896;
    constexpr int WOFF = TOFF + 33280;   // 50176
    constexpr int SCA = WOFF + 6528;     // 56704
    constexpr int SHA = SCA + 128;
    constexpr int SB1 = SHA + 128;       // ..57216
    extern __shared__ float sm[];
    const int tid = threadIdx.x, lane = tid & 31, wid = tid >> 5;
    const int bm = blockIdx.x * 128;
    const int qrow = lane >> 2, qk = lane & 3;
    const uint32_t smb = smem_to_u32(sm);

    // group 0: Y tile (128x128) + W1 chunk 0
    {
        int row = tid >> 2, cb = (tid & 3) * 32;
        bool ok = (bm + row) < Nn;
        const float* srcp = y + (size_t)(bm + row) * 128 + cb;
        uint32_t dst = smb + (uint32_t)(YOFF + row * 132 + cb) * 4u;
#pragma unroll
        for (int j = 0; j < 8; j++) cp16(dst + j * 16u, srcp + j * 4, ok);
    }
    {
        int r = tid >> 6, c = (tid & 63) * 4;
        cp16(smb + (uint32_t)(WOFF + r * 264 + c) * 4u, W1 + r * 256 + c, true);
    }
    CP_COMMIT();
    // group 1: W1 chunk 1
    {
        int r = tid >> 6, c = (tid & 63) * 4;
        cp16(smb + (uint32_t)(WOFF + 2112 + r * 264 + c) * 4u, W1 + (size_t)(8 + r) * 256 + c, true);
    }
    CP_COMMIT();

    const float invN = 1.f / (float)Nn;
    if (tid < 128) {
        float mu = slot1[tid] * invN;
        float var = slot1[tid + 128] * invN - mu * mu;
        float sc = g1[tid] * rsqrtf(var + EPSBN);
        sm[SCA + tid] = sc;
        sm[SHA + tid] = bb1[tid] - mu * sc;
    } else if (tid < 384) {
        sm[SB1 + tid - 128] = b1v[tid - 128];
    }

    // ---- stage A: T = relu(BN1(Y) @ W1 + b1), 16 chunks of K=8 ----
    const int m0A = (wid & 3) * 32, n0A = (wid >> 2) * 64;
    float accA[2][8][4];
#pragma unroll
    for (int mi = 0; mi < 2; mi++)
#pragma unroll
        for (int ni = 0; ni < 8; ni++)
#pragma unroll
            for (int j = 0; j < 4; j++) accA[mi][ni][j] = 0.f;

    for (int it = 0; it < 16; it++) {
        CP_WAIT1();        // chunk it (and Y at it=0) complete
        __syncthreads();   // all warps done with iter it-1 (buffer (it+2)%3 free)
        if (it + 2 < 16) {
            int r = tid >> 6, c = (tid & 63) * 4;
            cp16(smb + (uint32_t)(WOFF + ((it + 2) % 3) * 2112 + r * 264 + c) * 4u,
                 W1 + (size_t)((it + 2) * 8 + r) * 256 + c, true);
        }
        CP_COMMIT();
        const float* bs = sm + WOFF + (it % 3) * 2112;
        int kg = it * 8 + qk;
        float sc0 = sm[SCA + kg], sh0 = sm[SHA + kg];
        float sc1 = sm[SCA + kg + 4], sh1 = sm[SHA + kg + 4];
        uint32_t a[2][4];
#pragma unroll
        for (int mi = 0; mi < 2; mi++) {
            const float* ap = sm + YOFF + (m0A + mi * 16 + qrow) * 132 + it * 8 + qk;
            a[mi][0] = __float_as_uint(to_tf32(fmaf(ap[0], sc0, sh0)));
            a[mi][1] = __float_as_uint(to_tf32(fmaf(ap[8 * 132], sc0, sh0)));
            a[mi][2] = __float_as_uint(to_tf32(fmaf(ap[4], sc1, sh1)));
            a[mi][3] = __float_as_uint(to_tf32(fmaf(ap[8 * 132 + 4], sc1, sh1)));
        }
#pragma unroll
        for (int ni = 0; ni < 8; ni++) {
            uint32_t b[2];
            const float* bp = bs + qk * 264 + n0A + ni * 8 + qrow;
            b[0] = __float_as_uint(bp[0]);
            b[1] = __float_as_uint(bp[4 * 264]);
#pragma unroll
            for (int mi = 0; mi < 2; mi++) MMA_TF32(accA[mi][ni], a[mi], b);
        }
    }

    // write T = relu(acc + b1)
#pragma unroll
    for (int mi = 0; mi < 2; mi++) {
#pragma unroll
        for (int half = 0; half < 2; half++) {
            int rl = m0A + mi * 16 + half * 8 + qrow;
#pragma unroll
            for (int ni = 0; ni < 8; ni++) {
                int c = n0A + ni * 8 + qk * 2;
                float v0 = fmaxf(accA[mi][ni][half * 2 + 0] + sm[SB1 + c], 0.f);
                float v1 = fmaxf(accA[mi][ni][half * 2 + 1] + sm[SB1 + c + 1], 0.f);
                *(float2*)&sm[TOFF + rl * 260 + c] = make_float2(v0, v1);
            }
        }
    }
    __syncthreads();  // T visible; stage-A W buffers no longer read

    // ---- stage B: HC = T @ W2 + b2 + BN1(Y), 16 chunks of K=16 ----
    const int m0B = (wid & 3) * 32, n0B = (wid >> 2) * 32;
    float accB[2][4][4];
#pragma unroll
    for (int mi = 0; mi < 2; mi++)
#pragma unroll
        for (int ni = 0; ni < 4; ni++)
#pragma unroll
            for (int j = 0; j < 4; j++) accB[mi][ni][j] = 0.f;

    {
        int r = tid >> 5, c = (tid & 31) * 4;
        cp16(smb + (uint32_t)(WOFF + r * 136 + c) * 4u, W2 + r * 128 + c, true);
    }
    CP_COMMIT();
    {
        int r = tid >> 5, c = (tid & 31) * 4;
        cp16(smb + (uint32_t)(WOFF + 2176 + r * 136 + c) * 4u, W2 + (size_t)(16 + r) * 128 + c, true);
    }
    CP_COMMIT();

    for (int it = 0; it < 16; it++) {
        CP_WAIT1();
        __syncthreads();
        if (it + 2 < 16) {
            int r = tid >> 5, c = (tid & 31) * 4;
            cp16(smb + (uint32_t)(WOFF + ((it + 2) % 3) * 2176 + r * 136 + c) * 4u,
                 W2 + (size_t)((it + 2) * 16 + r) * 128 + c, true);
        }
        CP_COMMIT();
        const float* bs = sm + WOFF + (it % 3) * 2176;
#pragma unroll
        for (int ks = 0; ks < 2; ks++) {
            int kb = it * 16 + ks * 8;
            uint32_t a[2][4];
#pragma unroll
            for (int mi = 0; mi < 2; mi++) {
                const float* ap = sm + TOFF + (m0B + mi * 16 + qrow) * 260 + kb + qk;
                a[mi][0] = __float_as_uint(to_tf32(ap[0]));
                a[mi][1] = __float_as_uint(to_tf32(ap[8 * 260]));
                a[mi][2] = __float_as_uint(to_tf32(ap[4]));
                a[mi][3] = __float_as_uint(to_tf32(ap[8 * 260 + 4]));
            }
#pragma unroll
            for (int ni = 0; ni < 4; ni++) {
                uint32_t b[2];
                const float* bp = bs + (ks * 8 + qk) * 136 + n0B + ni * 8 + qrow;
                b[0] = __float_as_uint(bp[0]);
                b[1] = __float_as_uint(bp[4 * 136]);
#pragma unroll
                for (int mi = 0; mi < 2; mi++) MMA_TF32(accB[mi][ni], a[mi], b);
            }
        }
    }

    // epilogue: + b2 + BN1(y) residual, write HC, BN2 stats
    float s0[4], s1[4], q0[4], q1[4];
#pragma unroll
    for (int ni = 0; ni < 4; ni++) { s0[ni] = 0.f; s1[ni] = 0.f; q0[ni] = 0.f; q1[ni] = 0.f; }
#pragma unroll
    for (int mi = 0; mi < 2; mi++) {
#pragma unroll
        for (int half = 0; half < 2; half++) {
            int rl = m0B + mi * 16 + half * 8 + qrow;
            int r = bm + rl;
            bool rok = r < Nn;
#pragma unroll
            for (int ni = 0; ni < 4; ni++) {
                int gc = n0B + ni * 8 + qk * 2;
                float yv0 = fmaf(sm[YOFF + rl * 132 + gc], sm[SCA + gc], sm[SHA + gc]);
                float yv1 = fmaf(sm[YOFF + rl * 132 + gc + 1], sm[SCA + gc + 1], sm[SHA + gc + 1]);
                float v0 = accB[mi][ni][half * 2 + 0] + b2v[gc] + yv0;
                float v1 = accB[mi][ni][half * 2 + 1] + b2v[gc + 1] + yv1;
                if (rok) {
                    *(float2*)(C + (size_t)r * ldc + gc) = make_float2(v0, v1);
                    s0[ni] += v0; q0[ni] += v0 * v0;
                    s1[ni] += v1; q1[ni] += v1 * v1;
                }
            }
        }
    }
#pragma unroll
    for (int ni = 0; ni < 4; ni++) {
        s0[ni] += __shfl_xor_sync(0xffffffffu, s0[ni], 4);
        s0[ni] += __shfl_xor_sync(0xffffffffu, s0[ni], 8);
        s0[ni] += __shfl_xor_sync(0xffffffffu, s0[ni], 16);
        s1[ni] += __shfl_xor_sync(0xffffffffu, s1[ni], 4);
        s1[ni] += __shfl_xor_sync(0xffffffffu, s1[ni], 8);
        s1[ni] += __shfl_xor_sync(0xffffffffu, s1[ni], 16);
        q0[ni] += __shfl_xor_sync(0xffffffffu, q0[ni], 4);
        q0[ni] += __shfl_xor_sync(0xffffffffu, q0[ni], 8);
        q0[ni] += __shfl_xor_sync(0xffffffffu, q0[ni], 16);
        q1[ni] += __shfl_xor_sync(0xffffffffu, q1[ni], 4);
        q1[ni] += __shfl_xor_sync(0xffffffffu, q1[ni], 8);
        q1[ni] += __shfl_xor_sync(0xffffffffu, q1[ni], 16);
    }
    __syncthreads();
    if (lane < 4) {
        int mg = wid & 3;
#pragma unroll
        for (int ni = 0; ni < 4; ni++) {
            int c = n0B + ni * 8 + lane * 2;
            sm[mg * 128 + c] = s0[ni];
            sm[mg * 128 + c + 1] = s1[ni];
            sm[512 + mg * 128 + c] = q0[ni];
            sm[512 + mg * 128 + c + 1] = q1[ni];
        }
    }
    __syncthreads();
    if (tid < 256) {
        int c = tid & 127, st = tid >> 7;
        float v = sm[st * 512 + c] + sm[st * 512 + 128 + c] +
                  sm[st * 512 + 256 + c] + sm[st * 512 + 384 + c];
        atomicAdd(bnslot + st * 128 + c, v);
    }
}

// ---------------- GAT aggregate: single-pass softmax + prefetch + fused BN1 stats ----------------
__global__ void k_gat(const float* __restrict__ z,
                      const float* __restrict__ hres, int ldh,
                      const float* __restrict__ bias, float* __restrict__ y,
                      float* __restrict__ bnslot,
                      const float* __restrict__ slotPrev,
                      const float* __restrict__ gPrev, const float* __restrict__ bPrev) {
    __shared__ float sbn[2][8][128];
    int gw = (blockIdx.x * blockDim.x + threadIdx.x) >> 5;
    int lane = threadIdx.x & 31;
    int wid = threadIdx.x >> 5;
    float4 o = make_float4(0.f, 0.f, 0.f, 0.f);
    if (gw < Nn) {
        int head = lane >> 1;
        int beg = g_rowptr[gw], end = g_rowptr[gw + 1];
        float er_h = g_er[gw * 16 + head];
        const float4* z4 = (const float4*)z;

        float den = 0.f;
        float4 acc = make_float4(0.f, 0.f, 0.f, 0.f);
        float eN = 0.f;
        float4 zN = make_float4(0.f, 0.f, 0.f, 0.f);
        if (beg < end) {
            int s0i = g_srcs[beg];
            eN = g_el[s0i * 16 + head];
            zN = z4[(size_t)s0i * 32 + lane];
        }
        for (int i = beg; i < end; i++) {
            float e = eN + er_h;
            float4 zc = zN;
            if (i + 1 < end) {
                int s = g_srcs[i + 1];
                eN = g_el[s * 16 + head];
                zN = z4[(size_t)s * 32 + lane];
            }
            e = e > 0.f ? e : SLOPE * e;
            float w = __expf(e);
            den += w;
            acc.x += w * zc.x; acc.y += w * zc.y; acc.z += w * zc.z; acc.w += w * zc.w;
        }
        float dinv = den > 0.f ? 1.f / den : 1.f;
        float4 b4 = ((const float4*)bias)[lane];
        float4 h4 = *(const float4*)(hres + (size_t)gw * ldh + lane * 4);
        if (slotPrev != nullptr) {
            const float invN = 1.f / (float)Nn;
            int c = lane * 4;
#pragma unroll
            for (int j = 0; j < 4; j++) {
                float mu = slotPrev[c + j] * invN;
                float var = slotPrev[128 + c + j] * invN - mu * mu;
                float sc = gPrev[c + j] * rsqrtf(var + EPSBN);
                float sh = bPrev[c + j] - mu * sc;
                float* hp = (&h4.x) + j;
                *hp = fmaf(*hp, sc, sh);
            }
        }
        o.x = acc.x * dinv + b4.x + h4.x;
        o.y = acc.y * dinv + b4.y + h4.y;
        o.z = acc.z * dinv + b4.z + h4.z;
        o.w = acc.w * dinv + b4.w + h4.w;
        ((float4*)y)[(size_t)gw * 32 + lane] = o;
    }
    ((float4*)sbn[0][wid])[lane] = o;
    ((float4*)sbn[1][wid])[lane] = make_float4(o.x * o.x, o.y * o.y, o.z * o.z, o.w * o.w);
    __syncthreads();
    int c = threadIdx.x & 127, st = threadIdx.x >> 7;
    float v = 0.f;
#pragma unroll
    for (int w = 0; w < 8; w++) v += sbn[st][w][c];
    atomicAdd(bnslot + st * 128 + c, v);
}

// ---------------- launch ----------------
extern "C" void kernel_launch(void* const* d_in, const int* in_sizes, int n_in,
                              void* d_out, int out_size) {
    const float* x      = (const float*)d_in[0];
    const int*   src    = (const int*)d_in[1];
    const int*   dst    = (const int*)d_in[2];
    const float* emb_W1 = (const float*)d_in[3];
    const float* emb_b1 = (const float*)d_in[4];
    const float* emb_W2 = (const float*)d_in[5];
    const float* emb_b2 = (const float*)d_in[6];
    const float* emb_Ws = (const float*)d_in[7];
    const float* emb_bs = (const float*)d_in[8];
    const float* gat_W  = (const float*)d_in[9];
    const float* gat_al = (const float*)d_in[10];
    const float* gat_ar = (const float*)d_in[11];
    const float* gat_b  = (const float*)d_in[12];
    const float* bn1_g  = (const float*)d_in[13];
    const float* bn1_b  = (const float*)d_in[14];
    const float* ff_W1  = (const float*)d_in[15];
    const float* ff_b1  = (const float*)d_in[16];
    const float* ff_W2  = (const float*)d_in[17];
    const float* ff_b2  = (const float*)d_in[18];
    const float* bn2_g  = (const float*)d_in[19];
    const float* bn2_b  = (const float*)d_in[20];
    const float* dec_W1 = (const float*)d_in[21];
    const float* dec_b1 = (const float*)d_in[22];
    const float* dec_W2 = (const float*)d_in[23];
    const float* dec_b2 = (const float*)d_in[24];

    void* p;
    float *HC, *zb, *tb, *yb, *bns, *W;
    int* degp;
    cudaGetSymbolAddress(&p, g_HC);    HC = (float*)p;
    cudaGetSymbolAddress(&p, g_z);     zb = (float*)p;
    cudaGetSymbolAddress(&p, g_t);     tb = (float*)p;
    cudaGetSymbolAddress(&p, g_y);     yb = (float*)p;
    cudaGetSymbolAddress(&p, g_bnsum); bns = (float*)p;
    cudaGetSymbolAddress(&p, g_deg);   degp = (int*)p;
    cudaGetSymbolAddress(&p, g_W);     W = (float*)p;

    float* Wg = W;
    float* Wf1 = W + 65536;
    float* Wf2 = W + 196608;
    float* Wd = W + 327680;
    float* We2 = W + 409600;

    const int SMEM = 20736 * 4;        // 82944 B (generic)
    const int SMEM_FF = 57216 * 4;     // 228864 B (fused FF, triple-buffered W)
    static bool attrDone = false;
    if (!attrDone) {
        cudaFuncSetAttribute(k_tgemm<0, 0, 1, 0, 0, 0, 0, 0>, cudaFuncAttributeMaxDynamicSharedMemorySize, SMEM);
        cudaFuncSetAttribute(k_tgemm<0, 0, 0, 0, 1, 0, 0, 0>, cudaFuncAttributeMaxDynamicSharedMemorySize, SMEM);
        cudaFuncSetAttribute(k_tgemm<0, 0, 0, 0, 1, 1, 0, 0>, cudaFuncAttributeMaxDynamicSharedMemorySize, SMEM);
        cudaFuncSetAttribute(k_tgemm<1, 1, 0, 0, 0, 2, 0, 1>, cudaFuncAttributeMaxDynamicSharedMemorySize, SMEM);
        cudaFuncSetAttribute(k_ff, cudaFuncAttributeMaxDynamicSharedMemorySize, SMEM_FF);
        attrDone = true;
    }

    cudaMemsetAsync(bns, 0, 8 * 256 * sizeof(float));
    cudaMemsetAsync(degp, 0, Nn * sizeof(int));
    cudaMemsetAsync(d_out, 0, (size_t)out_size * sizeof(float));

    k_cvt_all<<<(425984 + 255) / 256, 256>>>(gat_W, ff_W1, ff_W2, dec_W1, emb_W2);
    k_embed1<<<(Nn * 128 + 255) / 256, 256>>>(x, emb_W1, emb_b1, emb_b2, emb_Ws, emb_bs);
    k_count<<<(Ee + 255) / 256, 256>>>(dst);

    const int gx = (Nn + 127) / 128;  // 782
    dim3 grid1(gx, 1);
    const int warpBlocks = (Nn * 32 + 255) / 256;

    // embed stage 2 GEMM
    k_tgemm<0, 0, 1, 0, 0, 0, 0, 0><<<grid1, 512, SMEM>>>(
        tb, 128, We2, nullptr, yb, 128, HC, 640, Nn, 128, 128, nullptr,
        nullptr, nullptr, nullptr, nullptr, nullptr, nullptr, nullptr, nullptr);

    const int nb = (Nn + 1023) / 1024;
    k_scan1<<<nb, 1024>>>();
    k_scan2<<<1, 128>>>(nb);
    k_finalize<<<(Nn + 255) / 256, 256>>>();
    k_fill<<<(Ee + 255) / 256, 256>>>(dst, src);

    for (int l = 0; l < 4; l++) {
        const float* h = HC + l * 128;
        float* slot1 = bns + (size_t)(2 * l) * 256;
        float* slot2 = bns + (size_t)(2 * l + 1) * 256;
        const float* slotP = (l > 0) ? (bns + (size_t)(2 * (l - 1) + 1) * 256) : nullptr;
        const float* gP = (l > 0) ? (bn2_g + (l - 1) * 128) : nullptr;
        const float* bP = (l > 0) ? (bn2_b + (l - 1) * 128) : nullptr;

        if (l == 0) {
            k_tgemm<0, 0, 0, 0, 1, 0, 0, 0><<<grid1, 512, SMEM>>>(
                h, 640, Wg, nullptr, nullptr, 0, zb, 128, Nn, 128, 128, nullptr,
                nullptr, nullptr, nullptr, nullptr, nullptr, nullptr,
                gat_al, gat_ar);
        } else {
            k_tgemm<0, 0, 0, 0, 1, 1, 0, 0><<<grid1, 512, SMEM>>>(
                h, 640, Wg + (size_t)l * 16384, nullptr, nullptr, 0, zb, 128, Nn, 128, 128, nullptr,
                slotP, gP, bP, nullptr, nullptr, nullptr,
                gat_al + l * 128, gat_ar + l * 128);
        }
        k_gat<<<warpBlocks, 256>>>(zb, h, 640, gat_b + l * 128, yb, slot1, slotP, gP, bP);
        k_ff<<<grid1, 512, SMEM_FF>>>(
            yb, Wf1 + (size_t)l * 32768, ff_b1 + l * 256,
            Wf2 + (size_t)l * 32768, ff_b2 + l * 128,
            HC + (size_t)(l + 1) * 128, 640,
            slot1, bn1_g + l * 128, bn1_b + l * 128, slot2);
    }

    // decoder: relu(affine_concat(HC) @ Wd + b1) . W2 + b2 (fused dot, atomic partials)
    k_tgemm<1, 1, 0, 0, 0, 2, 0, 1><<<grid1, 512, SMEM>>>(
        HC, 640, Wd, dec_b1, nullptr, 0, (float*)d_out, 1, Nn, 640, 128, nullptr,
        nullptr, bn2_g, bn2_b, nullptr, nullptr, nullptr, dec_W2, dec_b2);
}

// round 12
// speedup vs baseline: 1.0432x; 1.0432x over previous
#include <cuda_runtime.h>
#include <cstdint>

#define Nn 100000
#define Ee 600000
#define EPSBN 1e-5f
#define SLOPE 0.2f

// ---------------- scratch ----------------
__device__ float g_HC[(size_t)Nn * 640];
__device__ float g_z[(size_t)Nn * 128];
__device__ float g_t[(size_t)Nn * 256];
__device__ float g_y[(size_t)Nn * 128];
__device__ float g_el[(size_t)Nn * 16];
__device__ float g_er[(size_t)Nn * 16];
__device__ float g_bnsum[8 * 256];
__device__ int   g_deg[Nn];
__device__ int   g_scan[Nn];
__device__ int   g_bsum[128];
__device__ int   g_rowptr[Nn + 1];
__device__ int   g_cursor[Nn];
__device__ int   g_srcs[Ee];
__device__ float g_W[425984];

__device__ __forceinline__ float to_tf32(float x) {
    float r;
    asm("cvt.rna.tf32.f32 %0, %1;" : "=f"(r) : "f"(x));
    return r;
}
__device__ __forceinline__ uint32_t smem_to_u32(const void* p) {
    uint32_t a;
    asm("{ .reg .u64 t; cvta.to.shared.u64 t, %1; cvt.u32.u64 %0, t; }" : "=r"(a) : "l"(p));
    return a;
}
__device__ __forceinline__ void cp16(uint32_t dst, const void* src, bool ok) {
    int sz = ok ? 16 : 0;
    asm volatile("cp.async.cg.shared.global [%0], [%1], 16, %2;"
                 :: "r"(dst), "l"(src), "r"(sz) : "memory");
}
#define CP_COMMIT() asm volatile("cp.async.commit_group;" ::: "memory")
#define CP_WAIT2() asm volatile("cp.async.wait_group 2;" ::: "memory")
#define CP_WAIT1() asm volatile("cp.async.wait_group 1;" ::: "memory")
#define CP_WAIT0() asm volatile("cp.async.wait_group 0;" ::: "memory")

#define MMA_TF32(d, av, bv)                                               \
    asm volatile(                                                         \
        "mma.sync.aligned.m16n8k8.row.col.f32.tf32.tf32.f32 "             \
        "{%0,%1,%2,%3},{%4,%5,%6,%7},{%8,%9},{%0,%1,%2,%3};"              \
        : "+f"((d)[0]), "+f"((d)[1]), "+f"((d)[2]), "+f"((d)[3])          \
        : "r"((av)[0]), "r"((av)[1]), "r"((av)[2]), "r"((av)[3]),         \
          "r"((bv)[0]), "r"((bv)[1]))

// ---------------- CSR build ----------------
__global__ void k_count(const int* __restrict__ dst) {
    int e = blockIdx.x * blockDim.x + threadIdx.x;
    if (e < Ee) atomicAdd(&g_deg[dst[e]], 1);
}
__global__ void k_scan1() {
    __shared__ int s[1024];
    int i = blockIdx.x * 1024 + threadIdx.x;
    int v = (i < Nn) ? g_deg[i] : 0;
    s[threadIdx.x] = v;
    __syncthreads();
    for (int off = 1; off < 1024; off <<= 1) {
        int t = (threadIdx.x >= off) ? s[threadIdx.x - off] : 0;
        __syncthreads();
        s[threadIdx.x] += t;
        __syncthreads();
    }
    if (i < Nn) g_scan[i] = s[threadIdx.x];
    if (threadIdx.x == 1023) g_bsum[blockIdx.x] = s[1023];
}
__global__ void k_scan2(int nb) {
    __shared__ int s[128];
    int v = (threadIdx.x < nb) ? g_bsum[threadIdx.x] : 0;
    s[threadIdx.x] = v;
    __syncthreads();
    for (int off = 1; off < 128; off <<= 1) {
        int t = (threadIdx.x >= off) ? s[threadIdx.x - off] : 0;
        __syncthreads();
        s[threadIdx.x] += t;
        __syncthreads();
    }
    g_bsum[threadIdx.x] = (threadIdx.x == 0) ? 0 : s[threadIdx.x - 1];
}
__global__ void k_finalize() {
    int i = blockIdx.x * blockDim.x + threadIdx.x;
    if (i >= Nn) return;
    int incl = g_scan[i] + g_bsum[i >> 10];
    g_rowptr[i + 1] = incl;
    g_cursor[i] = incl - g_deg[i];
    if (i == 0) g_rowptr[0] = 0;
}
__global__ void k_fill(const int* __restrict__ dst, const int* __restrict__ src) {
    int e = blockIdx.x * blockDim.x + threadIdx.x;
    if (e < Ee) {
        int d = dst[e];
        int p = atomicAdd(&g_cursor[d], 1);
        g_srcs[p] = src[e];
    }
}

// ---------------- all-weight cvt ----------------
__global__ void k_cvt_all(const float* __restrict__ gat_W, const float* __restrict__ ff_W1,
                          const float* __restrict__ ff_W2, const float* __restrict__ dec_W1,
                          const float* __restrict__ emb_W2) {
    int i = blockIdx.x * blockDim.x + threadIdx.x;
    if (i >= 425984) return;
    float v;
    if (i < 65536) v = gat_W[i];
    else if (i < 196608) v = ff_W1[i - 65536];
    else if (i < 327680) v = ff_W2[i - 196608];
    else if (i < 409600) v = dec_W1[i - 327680];
    else v = emb_W2[i - 409600];
    g_W[i] = to_tf32(v);
}

// ---------------- embed stage 1 ----------------
__global__ void k_embed1(const float* __restrict__ x,
                         const float* __restrict__ W1, const float* __restrict__ b1,
                         const float* __restrict__ b2,
                         const float* __restrict__ Ws, const float* __restrict__ bs) {
    int idx = blockIdx.x * blockDim.x + threadIdx.x;
    if (idx >= Nn * 128) return;
    int n = idx >> 7, c = idx & 127;
    float x0 = x[n * 2], x1 = x[n * 2 + 1];
    float tv = fmaf(x0, W1[c], fmaf(x1, W1[128 + c], b1[c]));
    g_t[idx] = tv > 0.f ? tv : 0.f;
    g_y[idx] = fmaf(x0, Ws[c], fmaf(x1, Ws[128 + c], bs[c] + b2[c]));
}

// ---------------- generic fused tf32 tensor GEMM (512 thr) ----------------
template <int RELU, int BIAS, int RES, int BN, int ELER, int AAFF, int RAFF, int DEC>
__global__ void __launch_bounds__(512, 2) k_tgemm(
    const float* __restrict__ A, int lda,
    const float* __restrict__ B,
    const float* __restrict__ bias,
    const float* __restrict__ Res, int ldres,
    float* __restrict__ C, int ldc,
    int Nrows, int Mred, int Kcols, float* bnslot,
    const float* affA, const float* affAg, const float* affAb,
    const float* affR, const float* affRg, const float* affRb,
    const float* al, const float* ar) {
    constexpr int S = 4;
    constexpr int ASTG = 128 * 20;
    constexpr int BSTG = 16 * 136;
    constexpr int STGF = S * ASTG + S * BSTG;
    constexpr int SCA = STGF, SHA = SCA + 640, SCR = SHA + 640, SHR = SCR + 128;
    constexpr int ALO = SHR + 128, ARO = ALO + 128;
    extern __shared__ float sm[];
    float* AsF = sm;
    float* BsF = sm + S * ASTG;

    const int tid = threadIdx.x;
    const int lane = tid & 31;
    const int wid = tid >> 5;
    const int bm = blockIdx.x * 128;
    const int bn = blockIdx.y * 128;

    const int m0 = (wid & 3) * 32;
    const int n0 = (wid >> 2) * 32;
    const int qrow = lane >> 2;
    const int qk = lane & 3;

    const int arow = tid >> 2;
    const int aseg = (tid & 3) * 4;
    const int brow = tid >> 5;
    const int bcol = (tid & 31) * 4;

    const int gr = bm + arow;
    const bool aok = gr < Nrows;
    const float* Asrc = A + (size_t)gr * lda + aseg;
    const float* Bsrc = B + (size_t)brow * Kcols + bn + bcol;
    const uint32_t adst = smem_to_u32(AsF) + (uint32_t)(arow * 20 + aseg) * 4u;
    const uint32_t bdst = smem_to_u32(BsF) + (uint32_t)(brow * 136 + bcol) * 4u;

    const int nIter = Mred >> 4;

#pragma unroll
    for (int s = 0; s < S - 1; s++) {
        if (s < nIter) {
            int kt = s << 4;
            cp16(adst + (uint32_t)(s * ASTG) * 4u, Asrc + kt, aok);
            cp16(bdst + (uint32_t)(s * BSTG) * 4u, Bsrc + (size_t)kt * Kcols, true);
        }
        CP_COMMIT();
    }

    const float invN = 1.f / (float)Nn;
    if (AAFF) {
        for (int k = tid; k < Mred; k += 512) {
            float scv = 1.f, shv = 0.f;
            const float *slot = nullptr, *gg = nullptr, *bb = nullptr;
            int c = k;
            if (AAFF == 1) { slot = affA; gg = affAg; bb = affAb; }
            else {
                int blk = k >> 7;
                c = k & 127;
                if (blk > 0) {
                    slot = g_bnsum + (size_t)(2 * (blk - 1) + 1) * 256;
                    gg = affAg + (blk - 1) * 128;
                    bb = affAb + (blk - 1) * 128;
                }
            }
            if (slot) {
                float mu = slot[c] * invN;
                float var = slot[c + 128] * invN - mu * mu;
                float rs = rsqrtf(var + EPSBN);
                scv = gg[c] * rs;
                shv = bb[c] - mu * scv;
            }
            sm[SCA + k] = scv;
            sm[SHA + k] = shv;
        }
    }
    if (RAFF) {
        if (tid < 128) {
            float mu = affR[tid] * invN;
            float var = affR[tid + 128] * invN - mu * mu;
            float rs = rsqrtf(var + EPSBN);
            float scv = affRg[tid] * rs;
            sm[SCR + tid] = scv;
            sm[SHR + tid] = affRb[tid] - mu * scv;
        }
    }
    if (ELER) {
        if (tid < 128) sm[ALO + tid] = al[tid];
        else if (tid < 256) sm[ARO + tid - 128] = ar[tid - 128];
    }
    if (DEC) {
        if (tid < 128) sm[ALO + tid] = al[tid];
    }

    float acc[2][4][4];
#pragma unroll
    for (int mi = 0; mi < 2; mi++)
#pragma unroll
        for (int ni = 0; ni < 4; ni++)
#pragma unroll
            for (int j = 0; j < 4; j++) acc[mi][ni][j] = 0.f;

    for (int it = 0; it < nIter; it++) {
        CP_WAIT2();
        __syncthreads();

        const int stg = it & (S - 1);
        const float* as = AsF + stg * ASTG;
        const float* bs = BsF + stg * BSTG;
#pragma unroll
        for (int ks = 0; ks < 2; ks++) {
            const int kbase = ks * 8;
            float sc0 = 1.f, sc1 = 1.f, sh0 = 0.f, sh1 = 0.f;
            if (AAFF) {
                int kg = (it << 4) + kbase + qk;
                sc0 = sm[SCA + kg]; sh0 = sm[SHA + kg];
                sc1 = sm[SCA + kg + 4]; sh1 = sm[SHA + kg + 4];
            }
            uint32_t a[2][4];
#pragma unroll
            for (int mi = 0; mi < 2; mi++) {
                const float* ap = as + (m0 + mi * 16 + qrow) * 20 + kbase + qk;
                if (AAFF) {
                    a[mi][0] = __float_as_uint(to_tf32(fmaf(ap[0], sc0, sh0)));
                    a[mi][1] = __float_as_uint(to_tf32(fmaf(ap[8 * 20], sc0, sh0)));
                    a[mi][2] = __float_as_uint(to_tf32(fmaf(ap[4], sc1, sh1)));
                    a[mi][3] = __float_as_uint(to_tf32(fmaf(ap[8 * 20 + 4], sc1, sh1)));
                } else {
                    a[mi][0] = __float_as_uint(to_tf32(ap[0]));
                    a[mi][1] = __float_as_uint(to_tf32(ap[8 * 20]));
                    a[mi][2] = __float_as_uint(to_tf32(ap[4]));
                    a[mi][3] = __float_as_uint(to_tf32(ap[8 * 20 + 4]));
                }
            }
            uint32_t b[4][2];
#pragma unroll
            for (int ni = 0; ni < 4; ni++) {
                const float* bp = bs + (kbase + qk) * 136 + n0 + ni * 8 + qrow;
                b[ni][0] = __float_as_uint(bp[0]);
                b[ni][1] = __float_as_uint(bp[4 * 136]);
            }
#pragma unroll
            for (int mi = 0; mi < 2; mi++)
#pragma unroll
                for (int ni = 0; ni < 4; ni++) MMA_TF32(acc[mi][ni], a[mi], b[ni]);
        }

        const int nx = it + S - 1;
        if (nx < nIter) {
            const int s = nx & (S - 1);
            const int kt = nx << 4;
            cp16(adst + (uint32_t)(s * ASTG) * 4u, Asrc + kt, aok);
            cp16(bdst + (uint32_t)(s * BSTG) * 4u, Bsrc + (size_t)kt * Kcols, true);
        }
        CP_COMMIT();
    }

    // epilogue
    float s0[4], s1[4], q0[4], q1[4];
    if (BN) {
#pragma unroll
        for (int ni = 0; ni < 4; ni++) { s0[ni] = 0.f; s1[ni] = 0.f; q0[ni] = 0.f; q1[ni] = 0.f; }
    }
#pragma unroll
    for (int mi = 0; mi < 2; mi++) {
#pragma unroll
        for (int half = 0; half < 2; half++) {
            int r = bm + m0 + mi * 16 + qrow + half * 8;
            bool rok = r < Nrows;
            float pd = 0.f;
#pragma unroll
            for (int ni = 0; ni < 4; ni++) {
                int gcl = n0 + ni * 8 + qk * 2;
                int gc = bn + gcl;
                float v0 = acc[mi][ni][half * 2 + 0];
                float v1 = acc[mi][ni][half * 2 + 1];
                if (BIAS) {
                    v0 += bias[gc];
                    v1 += bias[gc + 1];
                }
                if (RELU) {
                    v0 = fmaxf(v0, 0.f);
                    v1 = fmaxf(v1, 0.f);
                }
                if (RES && rok) {
                    const float* rp = Res + (size_t)r * ldres + gc;
                    float rv0 = rp[0], rv1 = rp[1];
                    if (RAFF) {
                        rv0 = fmaf(rv0, sm[SCR + gc], sm[SHR + gc]);
                        rv1 = fmaf(rv1, sm[SCR + gc + 1], sm[SHR + gc + 1]);
                    }
                    v0 += rv0;
                    v1 += rv1;
                }
                if (!DEC && rok) *(float2*)(C + (size_t)r * ldc + gc) = make_float2(v0, v1);
                if (BN && rok) {
                    s0[ni] += v0; q0[ni] += v0 * v0;
                    s1[ni] += v1; q1[ni] += v1 * v1;
                }
                if (DEC) pd = fmaf(v0, sm[ALO + gcl], fmaf(v1, sm[ALO + gcl + 1], pd));
                if (ELER) {
                    int h = (n0 >> 3) + ni;
                    float p = fmaf(v0, sm[ALO + h * 8 + qk * 2], v1 * sm[ALO + h * 8 + qk * 2 + 1]);
                    float q = fmaf(v0, sm[ARO + h * 8 + qk * 2], v1 * sm[ARO + h * 8 + qk * 2 + 1]);
                    p += __shfl_xor_sync(0xffffffffu, p, 1);
                    p += __shfl_xor_sync(0xffffffffu, p, 2);
                    q += __shfl_xor_sync(0xffffffffu, q, 1);
                    q += __shfl_xor_sync(0xffffffffu, q, 2);
                    if ((lane & 3) == 0 && rok) {
                        g_el[r * 16 + h] = p;
                        g_er[r * 16 + h] = q;
                    }
                }
            }
            if (DEC) {
                pd += __shfl_xor_sync(0xffffffffu, pd, 1);
                pd += __shfl_xor_sync(0xffffffffu, pd, 2);
                if ((lane & 3) == 0 && rok)
                    atomicAdd(C + r, pd + 0.25f * ar[0]);
            }
        }
    }

    if (BN) {
#pragma unroll
        for (int ni = 0; ni < 4; ni++) {
            s0[ni] += __shfl_xor_sync(0xffffffffu, s0[ni], 4);
            s0[ni] += __shfl_xor_sync(0xffffffffu, s0[ni], 8);
            s0[ni] += __shfl_xor_sync(0xffffffffu, s0[ni], 16);
            s1[ni] += __shfl_xor_sync(0xffffffffu, s1[ni], 4);
            s1[ni] += __shfl_xor_sync(0xffffffffu, s1[ni], 8);
            s1[ni] += __shfl_xor_sync(0xffffffffu, s1[ni], 16);
            q0[ni] += __shfl_xor_sync(0xffffffffu, q0[ni], 4);
            q0[ni] += __shfl_xor_sync(0xffffffffu, q0[ni], 8);
            q0[ni] += __shfl_xor_sync(0xffffffffu, q0[ni], 16);
            q1[ni] += __shfl_xor_sync(0xffffffffu, q1[ni], 4);
            q1[ni] += __shfl_xor_sync(0xffffffffu, q1[ni], 8);
            q1[ni] += __shfl_xor_sync(0xffffffffu, q1[ni], 16);
        }
        __syncthreads();
        if (lane < 4) {
            int mg = wid & 3;
#pragma unroll
            for (int ni = 0; ni < 4; ni++) {
                int c = n0 + ni * 8 + lane * 2;
                sm[mg * 128 + c] = s0[ni];
                sm[mg * 128 + c + 1] = s1[ni];
                sm[512 + mg * 128 + c] = q0[ni];
                sm[512 + mg * 128 + c + 1] = q1[ni];
            }
        }
        __syncthreads();
        if (tid < 256) {
            int c = tid & 127, st = tid >> 7;
            float v = sm[st * 512 + c] + sm[st * 512 + 128 + c] +
                      sm[st * 512 + 256 + c] + sm[st * 512 + 384 + c];
            atomicAdd(bnslot + st * 128 + c, v);
        }
    }
}

// ---------------- fused FF kernel (R10 version: double-buffer, early prefetch) ----------------
// smem floats: Y[128][132]=16896 | T[128][260]=33280 | W 4352 | SCA 128 | SHA 128 | SB1 256
__global__ void __launch_bounds__(512, 1) k_ff(
    const float* __restrict__ y,
    const float* __restrict__ W1, const float* __restrict__ b1v,
    const float* __restrict__ W2, const float* __restrict__ b2v,
    float* __restrict__ C, int ldc,
    const float* __restrict__ slot1, const float* __restrict__ g1, const float* __restrict__ bb1,
    float* __restrict__ bnslot) {
    constexpr int YOFF = 0;
    constexpr int TOFF = 16896;
    constexpr int WOFF = TOFF + 33280;   // 50176
    constexpr int SCA = WOFF + 4352;     // 54528
    constexpr int SHA = SCA + 128;
    constexpr int SB1 = SHA + 128;       // ..55040
    extern __shared__ float sm[];
    const int tid = threadIdx.x, lane = tid & 31, wid = tid >> 5;
    const int bm = blockIdx.x * 128;
    const int qrow = lane >> 2, qk = lane & 3;
    const uint32_t smb = smem_to_u32(sm);

    // load full Y tile (128x128)
    {
        int row = tid >> 2, cb = (tid & 3) * 32;
        bool ok = (bm + row) < Nn;
        const float* srcp = y + (size_t)(bm + row) * 128 + cb;
        uint32_t dst = smb + (uint32_t)(YOFF + row * 132 + cb) * 4u;
#pragma unroll
        for (int j = 0; j < 8; j++) cp16(dst + j * 16u, srcp + j * 4, ok);
    }
    // W1 chunk 0 (rows 0..7 of [128][256])
    {
        int r = tid >> 6, c = (tid & 63) * 4;
        cp16(smb + (uint32_t)(WOFF + r * 264 + c) * 4u, W1 + r * 256 + c, true);
    }
    CP_COMMIT();
    const float invN = 1.f / (float)Nn;
    if (tid < 128) {
        float mu = slot1[tid] * invN;
        float var = slot1[tid + 128] * invN - mu * mu;
        float sc = g1[tid] * rsqrtf(var + EPSBN);
        sm[SCA + tid] = sc;
        sm[SHA + tid] = bb1[tid] - mu * sc;
    } else if (tid < 384) {
        sm[SB1 + tid - 128] = b1v[tid - 128];
    }
    CP_WAIT0();
    __syncthreads();

    // ---- stage A: T = relu(BN1(Y) @ W1 + b1), 16 chunks of K=8 ----
    const int m0A = (wid & 3) * 32, n0A = (wid >> 2) * 64;
    float accA[2][8][4];
#pragma unroll
    for (int mi = 0; mi < 2; mi++)
#pragma unroll
        for (int ni = 0; ni < 8; ni++)
#pragma unroll
            for (int j = 0; j < 4; j++) accA[mi][ni][j] = 0.f;

    for (int it = 0; it < 16; it++) {
        if (it + 1 < 16) {
            int r = tid >> 6, c = (tid & 63) * 4;
            cp16(smb + (uint32_t)(WOFF + ((it + 1) & 1) * 2112 + r * 264 + c) * 4u,
                 W1 + (size_t)((it + 1) * 8 + r) * 256 + c, true);
        }
        CP_COMMIT();
        CP_WAIT1();
        __syncthreads();
        const float* bs = sm + WOFF + (it & 1) * 2112;
        int kg = it * 8 + qk;
        float sc0 = sm[SCA + kg], sh0 = sm[SHA + kg];
        float sc1 = sm[SCA + kg + 4], sh1 = sm[SHA + kg + 4];
        uint32_t a[2][4];
#pragma unroll
        for (int mi = 0; mi < 2; mi++) {
            const float* ap = sm + YOFF + (m0A + mi * 16 + qrow) * 132 + it * 8 + qk;
            a[mi][0] = __float_as_uint(to_tf32(fmaf(ap[0], sc0, sh0)));
            a[mi][1] = __float_as_uint(to_tf32(fmaf(ap[8 * 132], sc0, sh0)));
            a[mi][2] = __float_as_uint(to_tf32(fmaf(ap[4], sc1, sh1)));
            a[mi][3] = __float_as_uint(to_tf32(fmaf(ap[8 * 132 + 4], sc1, sh1)));
        }
#pragma unroll
        for (int ni = 0; ni < 8; ni++) {
            uint32_t b[2];
            const float* bp = bs + qk * 264 + n0A + ni * 8 + qrow;
            b[0] = __float_as_uint(bp[0]);
            b[1] = __float_as_uint(bp[4 * 264]);
#pragma unroll
            for (int mi = 0; mi < 2; mi++) MMA_TF32(accA[mi][ni], a[mi], b);
        }
        __syncthreads();
    }

    // write T = relu(acc + b1)
#pragma unroll
    for (int mi = 0; mi < 2; mi++) {
#pragma unroll
        for (int half = 0; half < 2; half++) {
            int rl = m0A + mi * 16 + half * 8 + qrow;
#pragma unroll
            for (int ni = 0; ni < 8; ni++) {
                int c = n0A + ni * 8 + qk * 2;
                float v0 = fmaxf(accA[mi][ni][half * 2 + 0] + sm[SB1 + c], 0.f);
                float v1 = fmaxf(accA[mi][ni][half * 2 + 1] + sm[SB1 + c + 1], 0.f);
                *(float2*)&sm[TOFF + rl * 260 + c] = make_float2(v0, v1);
            }
        }
    }
    __syncthreads();

    // ---- stage B: HC = T @ W2 + b2 + BN1(Y), 16 chunks of K=16 ----
    const int m0B = (wid & 3) * 32, n0B = (wid >> 2) * 32;
    float accB[2][4][4];
#pragma unroll
    for (int mi = 0; mi < 2; mi++)
#pragma unroll
        for (int ni = 0; ni < 4; ni++)
#pragma unroll
            for (int j = 0; j < 4; j++) accB[mi][ni][j] = 0.f;

    {
        int r = tid >> 5, c = (tid & 31) * 4;
        cp16(smb + (uint32_t)(WOFF + r * 136 + c) * 4u, W2 + r * 128 + c, true);
    }
    CP_COMMIT();

    for (int it = 0; it < 16; it++) {
        if (it + 1 < 16) {
            int r = tid >> 5, c = (tid & 31) * 4;
            cp16(smb + (uint32_t)(WOFF + ((it + 1) & 1) * 2176 + r * 136 + c) * 4u,
                 W2 + (size_t)((it + 1) * 16 + r) * 128 + c, true);
        }
        CP_COMMIT();
        CP_WAIT1();
        __syncthreads();
        const float* bs = sm + WOFF + (it & 1) * 2176;
#pragma unroll
        for (int ks = 0; ks < 2; ks++) {
            int kb = it * 16 + ks * 8;
            uint32_t a[2][4];
#pragma unroll
            for (int mi = 0; mi < 2; mi++) {
                const float* ap = sm + TOFF + (m0B + mi * 16 + qrow) * 260 + kb + qk;
                a[mi][0] = __float_as_uint(to_tf32(ap[0]));
                a[mi][1] = __float_as_uint(to_tf32(ap[8 * 260]));
                a[mi][2] = __float_as_uint(to_tf32(ap[4]));
                a[mi][3] = __float_as_uint(to_tf32(ap[8 * 260 + 4]));
            }
#pragma unroll
            for (int ni = 0; ni < 4; ni++) {
                uint32_t b[2];
                const float* bp = bs + (ks * 8 + qk) * 136 + n0B + ni * 8 + qrow;
                b[0] = __float_as_uint(bp[0]);
                b[1] = __float_as_uint(bp[4 * 136]);
#pragma unroll
                for (int mi = 0; mi < 2; mi++) MMA_TF32(accB[mi][ni], a[mi], b);
            }
        }
        __syncthreads();
    }

    // epilogue: + b2 + BN1(y) residual, write HC, BN2 stats
    float s0[4], s1[4], q0[4], q1[4];
#pragma unroll
    for (int ni = 0; ni < 4; ni++) { s0[ni] = 0.f; s1[ni] = 0.f; q0[ni] = 0.f; q1[ni] = 0.f; }
#pragma unroll
    for (int mi = 0; mi < 2; mi++) {
#pragma unroll
        for (int half = 0; half < 2; half++) {
            int rl = m0B + mi * 16 + half * 8 + qrow;
            int r = bm + rl;
            bool rok = r < Nn;
#pragma unroll
            for (int ni = 0; ni < 4; ni++) {
                int gc = n0B + ni * 8 + qk * 2;
                float yv0 = fmaf(sm[YOFF + rl * 132 + gc], sm[SCA + gc], sm[SHA + gc]);
                float yv1 = fmaf(sm[YOFF + rl * 132 + gc + 1], sm[SCA + gc + 1], sm[SHA + gc + 1]);
                float v0 = accB[mi][ni][half * 2 + 0] + b2v[gc] + yv0;
                float v1 = accB[mi][ni][half * 2 + 1] + b2v[gc + 1] + yv1;
                if (rok) {
                    *(float2*)(C + (size_t)r * ldc + gc) = make_float2(v0, v1);
                    s0[ni] += v0; q0[ni] += v0 * v0;
                    s1[ni] += v1; q1[ni] += v1 * v1;
                }
            }
        }
    }
#pragma unroll
    for (int ni = 0; ni < 4; ni++) {
        s0[ni] += __shfl_xor_sync(0xffffffffu, s0[ni], 4);
        s0[ni] += __shfl_xor_sync(0xffffffffu, s0[ni], 8);
        s0[ni] += __shfl_xor_sync(0xffffffffu, s0[ni], 16);
        s1[ni] += __shfl_xor_sync(0xffffffffu, s1[ni], 4);
        s1[ni] += __shfl_xor_sync(0xffffffffu, s1[ni], 8);
        s1[ni] += __shfl_xor_sync(0xffffffffu, s1[ni], 16);
        q0[ni] += __shfl_xor_sync(0xffffffffu, q0[ni], 4);
        q0[ni] += __shfl_xor_sync(0xffffffffu, q0[ni], 8);
        q0[ni] += __shfl_xor_sync(0xffffffffu, q0[ni], 16);
        q1[ni] += __shfl_xor_sync(0xffffffffu, q1[ni], 4);
        q1[ni] += __shfl_xor_sync(0xffffffffu, q1[ni], 8);
        q1[ni] += __shfl_xor_sync(0xffffffffu, q1[ni], 16);
    }
    __syncthreads();
    if (lane < 4) {
        int mg = wid & 3;
#pragma unroll
        for (int ni = 0; ni < 4; ni++) {
            int c = n0B + ni * 8 + lane * 2;
            sm[mg * 128 + c] = s0[ni];
            sm[mg * 128 + c + 1] = s1[ni];
            sm[512 + mg * 128 + c] = q0[ni];
            sm[512 + mg * 128 + c + 1] = q1[ni];
        }
    }
    __syncthreads();
    if (tid < 256) {
        int c = tid & 127, st = tid >> 7;
        float v = sm[st * 512 + c] + sm[st * 512 + 128 + c] +
                  sm[st * 512 + 256 + c] + sm[st * 512 + 384 + c];
        atomicAdd(bnslot + st * 128 + c, v);
    }
}

// ---------------- GAT aggregate: single-pass softmax, 2-way edge unroll, fused BN1 stats ----------------
__global__ void k_gat(const float* __restrict__ z,
                      const float* __restrict__ hres, int ldh,
                      const float* __restrict__ bias, float* __restrict__ y,
                      float* __restrict__ bnslot,
                      const float* __restrict__ slotPrev,
                      const float* __restrict__ gPrev, const float* __restrict__ bPrev) {
    __shared__ float sbn[2][8][128];
    int gw = (blockIdx.x * blockDim.x + threadIdx.x) >> 5;
    int lane = threadIdx.x & 31;
    int wid = threadIdx.x >> 5;
    float4 o = make_float4(0.f, 0.f, 0.f, 0.f);
    if (gw < Nn) {
        int head = lane >> 1;
        int beg = g_rowptr[gw], end = g_rowptr[gw + 1];
        float er_h = g_er[gw * 16 + head];
        const float4* z4 = (const float4*)z;

        float den = 0.f;
        float4 acc = make_float4(0.f, 0.f, 0.f, 0.f);
        int i = beg;
        for (; i + 1 < end; i += 2) {
            int sA = g_srcs[i];
            int sB = g_srcs[i + 1];
            float eA = g_el[sA * 16 + head];
            float eB = g_el[sB * 16 + head];
            float4 zA = z4[(size_t)sA * 32 + lane];
            float4 zB = z4[(size_t)sB * 32 + lane];
            eA += er_h;
            eB += er_h;
            eA = eA > 0.f ? eA : SLOPE * eA;
            eB = eB > 0.f ? eB : SLOPE * eB;
            float wA = __expf(eA);
            float wB = __expf(eB);
            den += wA + wB;
            acc.x += wA * zA.x + wB * zB.x;
            acc.y += wA * zA.y + wB * zB.y;
            acc.z += wA * zA.z + wB * zB.z;
            acc.w += wA * zA.w + wB * zB.w;
        }
        if (i < end) {
            int s = g_srcs[i];
            float e = g_el[s * 16 + head] + er_h;
            float4 zc = z4[(size_t)s * 32 + lane];
            e = e > 0.f ? e : SLOPE * e;
            float w = __expf(e);
            den += w;
            acc.x += w * zc.x; acc.y += w * zc.y; acc.z += w * zc.z; acc.w += w * zc.w;
        }
        float dinv = den > 0.f ? 1.f / den : 1.f;
        float4 b4 = ((const float4*)bias)[lane];
        float4 h4 = *(const float4*)(hres + (size_t)gw * ldh + lane * 4);
        if (slotPrev != nullptr) {
            const float invN = 1.f / (float)Nn;
            int c = lane * 4;
#pragma unroll
            for (int j = 0; j < 4; j++) {
                float mu = slotPrev[c + j] * invN;
                float var = slotPrev[128 + c + j] * invN - mu * mu;
                float sc = gPrev[c + j] * rsqrtf(var + EPSBN);
                float sh = bPrev[c + j] - mu * sc;
                float* hp = (&h4.x) + j;
                *hp = fmaf(*hp, sc, sh);
            }
        }
        o.x = acc.x * dinv + b4.x + h4.x;
        o.y = acc.y * dinv + b4.y + h4.y;
        o.z = acc.z * dinv + b4.z + h4.z;
        o.w = acc.w * dinv + b4.w + h4.w;
        ((float4*)y)[(size_t)gw * 32 + lane] = o;
    }
    ((float4*)sbn[0][wid])[lane] = o;
    ((float4*)sbn[1][wid])[lane] = make_float4(o.x * o.x, o.y * o.y, o.z * o.z, o.w * o.w);
    __syncthreads();
    int c = threadIdx.x & 127, st = threadIdx.x >> 7;
    float v = 0.f;
#pragma unroll
    for (int w = 0; w < 8; w++) v += sbn[st][w][c];
    atomicAdd(bnslot + st * 128 + c, v);
}

// ---------------- launch ----------------
extern "C" void kernel_launch(void* const* d_in, const int* in_sizes, int n_in,
                              void* d_out, int out_size) {
    const float* x      = (const float*)d_in[0];
    const int*   src    = (const int*)d_in[1];
    const int*   dst    = (const int*)d_in[2];
    const float* emb_W1 = (const float*)d_in[3];
    const float* emb_b1 = (const float*)d_in[4];
    const float* emb_W2 = (const float*)d_in[5];
    const float* emb_b2 = (const float*)d_in[6];
    const float* emb_Ws = (const float*)d_in[7];
    const float* emb_bs = (const float*)d_in[8];
    const float* gat_W  = (const float*)d_in[9];
    const float* gat_al = (const float*)d_in[10];
    const float* gat_ar = (const float*)d_in[11];
    const float* gat_b  = (const float*)d_in[12];
    const float* bn1_g  = (const float*)d_in[13];
    const float* bn1_b  = (const float*)d_in[14];
    const float* ff_W1  = (const float*)d_in[15];
    const float* ff_b1  = (const float*)d_in[16];
    const float* ff_W2  = (const float*)d_in[17];
    const float* ff_b2  = (const float*)d_in[18];
    const float* bn2_g  = (const float*)d_in[19];
    const float* bn2_b  = (const float*)d_in[20];
    const float* dec_W1 = (const float*)d_in[21];
    const float* dec_b1 = (const float*)d_in[22];
    const float* dec_W2 = (const float*)d_in[23];
    const float* dec_b2 = (const float*)d_in[24];

    void* p;
    float *HC, *zb, *tb, *yb, *bns, *W;
    int* degp;
    cudaGetSymbolAddress(&p, g_HC);    HC = (float*)p;
    cudaGetSymbolAddress(&p, g_z);     zb = (float*)p;
    cudaGetSymbolAddress(&p, g_t);     tb = (float*)p;
    cudaGetSymbolAddress(&p, g_y);     yb = (float*)p;
    cudaGetSymbolAddress(&p, g_bnsum); bns = (float*)p;
    cudaGetSymbolAddress(&p, g_deg);   degp = (int*)p;
    cudaGetSymbolAddress(&p, g_W);     W = (float*)p;

    float* Wg = W;
    float* Wf1 = W + 65536;
    float* Wf2 = W + 196608;
    float* Wd = W + 327680;
    float* We2 = W + 409600;

    const int SMEM = 20736 * 4;        // 82944 B (generic)
    const int SMEM_FF = 55040 * 4;     // 220160 B (fused FF, R10 layout)
    static bool attrDone = false;
    if (!attrDone) {
        cudaFuncSetAttribute(k_tgemm<0, 0, 1, 0, 0, 0, 0, 0>, cudaFuncAttributeMaxDynamicSharedMemorySize, SMEM);
        cudaFuncSetAttribute(k_tgemm<0, 0, 0, 0, 1, 0, 0, 0>, cudaFuncAttributeMaxDynamicSharedMemorySize, SMEM);
        cudaFuncSetAttribute(k_tgemm<0, 0, 0, 0, 1, 1, 0, 0>, cudaFuncAttributeMaxDynamicSharedMemorySize, SMEM);
        cudaFuncSetAttribute(k_tgemm<1, 1, 0, 0, 0, 2, 0, 1>, cudaFuncAttributeMaxDynamicSharedMemorySize, SMEM);
        cudaFuncSetAttribute(k_ff, cudaFuncAttributeMaxDynamicSharedMemorySize, SMEM_FF);
        attrDone = true;
    }

    cudaMemsetAsync(bns, 0, 8 * 256 * sizeof(float));
    cudaMemsetAsync(degp, 0, Nn * sizeof(int));
    cudaMemsetAsync(d_out, 0, (size_t)out_size * sizeof(float));

    k_cvt_all<<<(425984 + 255) / 256, 256>>>(gat_W, ff_W1, ff_W2, dec_W1, emb_W2);
    k_embed1<<<(Nn * 128 + 255) / 256, 256>>>(x, emb_W1, emb_b1, emb_b2, emb_Ws, emb_bs);
    k_count<<<(Ee + 255) / 256, 256>>>(dst);

    const int gx = (Nn + 127) / 128;  // 782
    dim3 grid1(gx, 1);
    const int warpBlocks = (Nn * 32 + 255) / 256;

    // embed stage 2 GEMM
    k_tgemm<0, 0, 1, 0, 0, 0, 0, 0><<<grid1, 512, SMEM>>>(
        tb, 128, We2, nullptr, yb, 128, HC, 640, Nn, 128, 128, nullptr,
        nullptr, nullptr, nullptr, nullptr, nullptr, nullptr, nullptr, nullptr);

    const int nb = (Nn + 1023) / 1024;
    k_scan1<<<nb, 1024>>>();
    k_scan2<<<1, 128>>>(nb);
    k_finalize<<<(Nn + 255) / 256, 256>>>();
    k_fill<<<(Ee + 255) / 256, 256>>>(dst, src);

    for (int l = 0; l < 4; l++) {
        const float* h = HC + l * 128;
        float* slot1 = bns + (size_t)(2 * l) * 256;
        float* slot2 = bns + (size_t)(2 * l + 1) * 256;
        const float* slotP = (l > 0) ? (bns + (size_t)(2 * (l - 1) + 1) * 256) : nullptr;
        const float* gP = (l > 0) ? (bn2_g + (l - 1) * 128) : nullptr;
        const float* bP = (l > 0) ? (bn2_b + (l - 1) * 128) : nullptr;

        if (l == 0) {
            k_tgemm<0, 0, 0, 0, 1, 0, 0, 0><<<grid1, 512, SMEM>>>(
                h, 640, Wg, nullptr, nullptr, 0, zb, 128, Nn, 128, 128, nullptr,
                nullptr, nullptr, nullptr, nullptr, nullptr, nullptr,
                gat_al, gat_ar);
        } else {
            k_tgemm<0, 0, 0, 0, 1, 1, 0, 0><<<grid1, 512, SMEM>>>(
                h, 640, Wg + (size_t)l * 16384, nullptr, nullptr, 0, zb, 128, Nn, 128, 128, nullptr,
                slotP, gP, bP, nullptr, nullptr, nullptr,
                gat_al + l * 128, gat_ar + l * 128);
        }
        k_gat<<<warpBlocks, 256>>>(zb, h, 640, gat_b + l * 128, yb, slot1, slotP, gP, bP);
        k_ff<<<grid1, 512, SMEM_FF>>>(
            yb, Wf1 + (size_t)l * 32768, ff_b1 + l * 256,
            Wf2 + (size_t)l * 32768, ff_b2 + l * 128,
            HC + (size_t)(l + 1) * 128, 640,
            slot1, bn1_g + l * 128, bn1_b + l * 128, slot2);
    }

    // decoder: relu(affine_concat(HC) @ Wd + b1) . W2 + b2 (fused dot, atomic partials)
    k_tgemm<1, 1, 0, 0, 0, 2, 0, 1><<<grid1, 512, SMEM>>>(
        HC, 640, Wd, dec_b1, nullptr, 0, (float*)d_out, 1, Nn, 640, 128, nullptr,
        nullptr, bn2_g, bn2_b, nullptr, nullptr, nullptr, dec_W2, dec_b2);
}